// round 1
// baseline (speedup 1.0000x reference)
#include <cuda_runtime.h>
#include <cstdint>

// ---------------- problem constants ----------------
#define B_  8
#define T_  64
#define D_  256
#define H_  1024
#define CPB 8            // CTAs per batch (cluster size)
#define SLICE (H_/CPB)   // 128 rows of H per CTA
#define NTHREADS 256
#define LR    1e-3f
#define DECAY 0.02f
#define MU    0.9f
#define EPS_  1e-6f

#define CLUSTER_SYNC() do { \
    asm volatile("barrier.cluster.arrive.aligned;" ::: "memory"); \
    asm volatile("barrier.cluster.wait.aligned;"  ::: "memory"); } while (0)

// ---------------- device scratch (no allocs allowed) ----------------
__device__ float g_XN[B_*T_*D_];        // normalized keys
__device__ float g_GRAM[B_*T_*T_];      // G[b][t][r] = xn_t . xn_r
__device__ float g_P1[B_*T_*H_];        // w1_0 @ xn_t  (fixed forward term)
__device__ float g_A2[B_*T_*D_];        // dpred history (rank factor for w2)
__device__ float g_RED1[B_][CPB][D_+T_+1];
__device__ float g_RED2[B_][CPB];

// ---------------- precompute: normalize keys ----------------
__global__ void k_norm(const float* __restrict__ keys)
{
    int bt = blockIdx.x, tid = threadIdx.x;
    float v = keys[bt*D_ + tid];
    float ss = v*v;
    #pragma unroll
    for (int o=16;o;o>>=1) ss += __shfl_xor_sync(~0u, ss, o);
    __shared__ float ws[8];
    __shared__ float s_scale;
    if ((tid&31)==0) ws[tid>>5] = ss;
    __syncthreads();
    if (tid==0) {
        float tot=0.f;
        #pragma unroll
        for (int i=0;i<8;i++) tot += ws[i];
        s_scale = 1.0f / fmaxf(sqrtf(tot), 1e-12f);
    }
    __syncthreads();
    g_XN[bt*D_ + tid] = v * s_scale;
}

// ---------------- precompute: Gram matrix of normalized keys ----------------
__global__ void k_gram()
{
    int bt = blockIdx.x, b = bt / T_, t = bt % T_;
    int tid = threadIdx.x, lane = tid&31, w = tid>>5;
    __shared__ float xt[D_];
    xt[tid] = g_XN[bt*D_ + tid];
    __syncthreads();
    for (int r = w; r < T_; r += 8) {
        const float* xr = &g_XN[(b*T_+r)*D_];
        float acc = 0.f;
        #pragma unroll
        for (int k=lane; k<D_; k+=32) acc += xr[k]*xt[k];
        #pragma unroll
        for (int o=16;o;o>>=1) acc += __shfl_xor_sync(~0u, acc, o);
        if (lane==0) g_GRAM[(b*T_+t)*T_ + r] = acc;
    }
}

// ---------------- precompute: P1[b,t,:] = w1_0 @ xn[b,t] ----------------
__global__ void k_p1(const float* __restrict__ w1)
{
    int hc = blockIdx.x;      // 16 chunks of 64 H-rows
    int b  = blockIdx.y;
    int tid = threadIdx.x, lane = tid&31, w = tid>>5;
    __shared__ float xns[32][D_];
    for (int half = 0; half < 2; half++) {
        for (int idx = tid; idx < 32*D_; idx += NTHREADS) {
            int tt = idx / D_, d = idx % D_;
            xns[tt][d] = g_XN[(b*T_ + half*32 + tt)*D_ + d];
        }
        __syncthreads();
        for (int j = 0; j < 8; j++) {
            int h = hc*64 + w*8 + j;
            float wr[8];
            #pragma unroll
            for (int k=0;k<8;k++) wr[k] = w1[h*D_ + lane + 32*k];
            for (int tt = 0; tt < 32; tt++) {
                float acc = 0.f;
                #pragma unroll
                for (int k=0;k<8;k++) acc += wr[k]*xns[tt][lane + 32*k];
                #pragma unroll
                for (int o=16;o;o>>=1) acc += __shfl_xor_sync(~0u, acc, o);
                if (lane==0) g_P1[(b*T_ + half*32 + tt)*H_ + h] = acc;
            }
        }
        __syncthreads();
    }
}

// ---------------- main sequential kernel: 1 cluster of 8 CTAs per batch ----------------
__global__ __launch_bounds__(NTHREADS, 1) __cluster_dims__(CPB, 1, 1)
void k_main(const float* __restrict__ values, const float* __restrict__ w2,
            float* __restrict__ out_preds, float* __restrict__ out_surp)
{
    extern __shared__ float sm[];
    float* w2s  = sm;                         // [SLICE][D_+1]  w2_0 column slice
    float* A1s  = w2s  + SLICE*(D_+1);        // [T_][SLICE]    dh_pre history slice
    float* B2s  = A1s  + T_*SLICE;            // [T_][SLICE+1]  h history slice
    float* h_s  = B2s  + T_*(SLICE+1);        // [SLICE]
    float* gp_s = h_s  + SLICE;               // [SLICE] gelu'
    float* dp_s = gp_s + SLICE;               // [D_]
    float* red_s= dp_s + D_;                  // [D_+T_+1] reduced partials
    float* cf_s = red_s+ (D_+T_+1);           // [T_] per-phase coefficients
    float* Pc   = cf_s + T_;                  // [T_] param coeffs (shared w1/w2)
    float* Mc   = Pc   + T_;                  // [T_] momentum coeffs
    float* rs   = Mc   + T_;                  // [8] warp-reduce scratch
    float* sc   = rs   + 8;                   // scalars: 0=alpha 1=hn2(part) 2=dn2 3=clip 4=gtt

    int tid = threadIdx.x, lane = tid&31, wid = tid>>5;
    int b     = blockIdx.x / CPB;
    int crank = blockIdx.x % CPB;
    int base  = crank * SLICE;

    // stage w2_0 slice into smem (transposed, pad-257 -> conflict-free both ways)
    for (int idx = tid; idx < D_*SLICE; idx += NTHREADS) {
        int d = idx >> 7, il = idx & (SLICE-1);
        w2s[il*(D_+1) + d] = w2[d*H_ + base + il];
    }
    if (tid < T_) { Pc[tid] = 0.f; Mc[tid] = 0.f; }
    if (tid == 0) sc[0] = 1.0f;
    __syncthreads();

    for (int t = 0; t < T_; t++) {
        float alpha = sc[0];
        // coefficients for forward-w1 rank part: Pc[r] * Gram[t][r]
        if (tid < t)  cf_s[tid] = Pc[tid] * g_GRAM[(b*T_+t)*T_ + tid];
        if (tid == 0) sc[4] = g_GRAM[(b*T_+t)*T_ + t];     // ||xn_t||^2
        __syncthreads();

        // ---- phase 2: h slice = gelu(alpha*P1 + A1 @ coef) ----
        float hh2 = 0.f;
        if (tid < SLICE) {
            float z = alpha * g_P1[(b*T_+t)*H_ + base + tid];
            #pragma unroll 4
            for (int r=0;r<t;r++) z += cf_s[r]*A1s[r*SLICE + tid];
            float ph = 0.5f*(1.0f + erff(z*0.70710678118654752f));
            float h  = z*ph;
            float gp = ph + z*0.39894228040143268f*expf(-0.5f*z*z);
            h_s[tid] = h; gp_s[tid] = gp;
            B2s[t*(SLICE+1) + tid] = h;
            hh2 = h*h;
        }
        #pragma unroll
        for (int o=16;o;o>>=1) hh2 += __shfl_xor_sync(~0u, hh2, o);
        if (lane==0) rs[wid] = hh2;
        __syncthreads();
        if (tid==0){ float s=0.f; for(int i=0;i<8;i++) s+=rs[i]; sc[1]=s; }
        __syncthreads();

        // ---- phase 3a: partial pred (w2_0 slice) + partial v (B2 slice) ----
        {
            float acc = 0.f;
            int d = tid;
            #pragma unroll 8
            for (int i=0;i<SLICE;i++) acc += w2s[i*(D_+1)+d]*h_s[i];
            g_RED1[b][crank][d] = acc;
            if (tid < t) {
                float av = 0.f;
                #pragma unroll 8
                for (int i=0;i<SLICE;i++) av += B2s[tid*(SLICE+1)+i]*h_s[i];
                g_RED1[b][crank][D_+tid] = av;
            }
            if (tid==0) g_RED1[b][crank][D_+T_] = sc[1];
        }
        CLUSTER_SYNC();

        // ---- phase 3b: reduce, pred, dpred ----
        for (int k = tid; k < D_+T_+1; k += NTHREADS) {
            float s = 0.f;
            #pragma unroll
            for (int j=0;j<CPB;j++) s += g_RED1[b][j][k];
            red_s[k] = s;
        }
        __syncthreads();
        if (tid < t) cf_s[tid] = Pc[tid] * red_s[D_+tid];   // Pc[r]*v_r
        __syncthreads();
        float dn2p;
        {
            int d = tid;
            float pr = alpha * red_s[d];
            #pragma unroll 4
            for (int r=0;r<t;r++) pr += cf_s[r]*g_A2[(b*T_+r)*D_ + d];
            float vv = values[(b*T_+t)*D_ + d];
            float dp = 2.0f*(pr - vv);
            dp_s[d] = dp;
            if (crank==0) {
                out_preds[(b*T_+t)*D_ + d] = pr;
                g_A2[(b*T_+t)*D_ + d] = dp;
            }
            dn2p = dp*dp;
        }
        #pragma unroll
        for (int o=16;o;o>>=1) dn2p += __shfl_xor_sync(~0u, dn2p, o);
        if (lane==0) rs[wid] = dn2p;
        __syncthreads();
        if (tid==0){ float s=0.f; for(int i=0;i<8;i++) s+=rs[i]; sc[2]=s; }
        __syncthreads();

        // ---- phase 4: dh slice = alpha*w2_0^T dpred + B2 @ (Pc*(A2^T dpred)) ----
        for (int r = wid; r < t; r += 8) {                   // warp-per-rank dots
            const float* a2r = &g_A2[(b*T_+r)*D_];
            float acc = 0.f;
            #pragma unroll
            for (int d=lane; d<D_; d+=32) acc += a2r[d]*dp_s[d];
            #pragma unroll
            for (int o=16;o;o>>=1) acc += __shfl_xor_sync(~0u, acc, o);
            if (lane==0) cf_s[r] = Pc[r]*acc;
        }
        __syncthreads();
        float gn2p = 0.f;
        if (tid < SLICE) {
            int i = tid;
            float fx = 0.f;
            #pragma unroll 8
            for (int d=0; d<D_; d++) fx += w2s[i*(D_+1)+d]*dp_s[d];
            float dh = alpha*fx;
            #pragma unroll 4
            for (int r=0;r<t;r++) dh += cf_s[r]*B2s[r*(SLICE+1)+i];
            float dhp = dh * gp_s[i];
            A1s[t*SLICE + i] = dhp;
            gn2p = dhp*dhp;
        }
        #pragma unroll
        for (int o=16;o;o>>=1) gn2p += __shfl_xor_sync(~0u, gn2p, o);
        if (lane==0) rs[wid] = gn2p;
        __syncthreads();
        if (tid==0){ float s=0.f; for(int i=0;i<8;i++) s+=rs[i]; g_RED2[b][crank]=s; }
        CLUSTER_SYNC();

        // ---- phase 5: gnorm, clip, coefficient recurrences ----
        if (tid==0) {
            float dhn2 = 0.f;
            #pragma unroll
            for (int j=0;j<CPB;j++) dhn2 += g_RED2[b][j];
            float gn = sqrtf(dhn2*sc[4] + sc[2]*red_s[D_+T_]);
            sc[3] = fminf(1.0f/(gn + EPS_), 1.0f);
            if (crank==0) out_surp[b*T_ + t] = gn;
            sc[0] = alpha*(1.0f - DECAY);
        }
        __syncthreads();
        {
            float clip = sc[3];
            if (tid < t) {
                float m = Mc[tid]*MU;
                Mc[tid] = m;
                Pc[tid] = Pc[tid]*(1.0f - DECAY) - LR*m;
            } else if (tid == t) {
                Mc[t] = clip;
                Pc[t] = -LR*clip;
            }
        }
        __syncthreads();
    }
}

// ---------------- launch ----------------
extern "C" void kernel_launch(void* const* d_in, const int* in_sizes, int n_in,
                              void* d_out, int out_size)
{
    (void)in_sizes; (void)n_in; (void)out_size;
    const float* keys   = (const float*)d_in[0];
    const float* values = (const float*)d_in[1];
    const float* w1     = (const float*)d_in[2];
    const float* w2     = (const float*)d_in[3];
    float* out       = (float*)d_out;
    float* out_preds = out;                 // [B,T,D]
    float* out_surp  = out + B_*T_*D_;      // [B,T]

    k_norm<<<B_*T_, D_>>>(keys);
    k_gram<<<B_*T_, 256>>>();
    dim3 gp1(H_/64, B_);
    k_p1<<<gp1, NTHREADS>>>(w1);

    const size_t smem_bytes =
        (size_t)( SLICE*(D_+1) + T_*SLICE + T_*(SLICE+1)
                + SLICE + SLICE + D_ + (D_+T_+1) + T_ + T_ + T_ + 8 + 8 ) * sizeof(float);
    cudaFuncSetAttribute(k_main, cudaFuncAttributeMaxDynamicSharedMemorySize,
                         (int)smem_bytes);
    k_main<<<B_*CPB, NTHREADS, smem_bytes>>>(values, w2, out_preds, out_surp);
}

// round 2
// speedup vs baseline: 1.2658x; 1.2658x over previous
#include <cuda_runtime.h>
#include <cuda_bf16.h>
#include <cstdint>

// ---------------- problem constants ----------------
#define B_  8
#define T_  64
#define D_  256
#define H_  1024
#define CPB 8            // CTAs per batch (cluster size)
#define SLICE 128        // H rows per CTA
#define NT  256
#define LR    1e-3f
#define DECAY 0.02f
#define MU    0.9f
#define EPS_  1e-6f

#define CLUSTER_SYNC() do { \
    asm volatile("barrier.cluster.arrive.aligned;" ::: "memory"); \
    asm volatile("barrier.cluster.wait.aligned;"  ::: "memory"); } while (0)

// ---------------- device scratch ----------------
__device__ float g_XN[B_*T_*D_];        // normalized keys
__device__ float g_GRAM[B_*T_*T_];      // G[b][t][r] = xn_t . xn_r
__device__ float g_P1[B_*T_*H_];        // w1_0 @ xn_t
__device__ float g_RED1[B_][CPB][D_+T_+1];
__device__ float g_RED2[B_][CPB];

// ---------------- precompute: normalize keys ----------------
__global__ void k_norm(const float* __restrict__ keys)
{
    int bt = blockIdx.x, tid = threadIdx.x;
    float v = keys[bt*D_ + tid];
    float ss = v*v;
    #pragma unroll
    for (int o=16;o;o>>=1) ss += __shfl_xor_sync(~0u, ss, o);
    __shared__ float ws[8];
    __shared__ float s_scale;
    if ((tid&31)==0) ws[tid>>5] = ss;
    __syncthreads();
    if (tid==0) {
        float tot=0.f;
        #pragma unroll
        for (int i=0;i<8;i++) tot += ws[i];
        s_scale = 1.0f / fmaxf(sqrtf(tot), 1e-12f);
    }
    __syncthreads();
    g_XN[bt*D_ + tid] = v * s_scale;
}

// ---------------- precompute: Gram matrix ----------------
__global__ void k_gram()
{
    int bt = blockIdx.x, b = bt / T_, t = bt % T_;
    int tid = threadIdx.x, lane = tid&31, w = tid>>5;
    __shared__ float xt[D_];
    xt[tid] = g_XN[bt*D_ + tid];
    __syncthreads();
    for (int r = w; r < T_; r += 8) {
        const float* xr = &g_XN[(b*T_+r)*D_];
        float acc = 0.f;
        #pragma unroll
        for (int k=lane; k<D_; k+=32) acc += xr[k]*xt[k];
        #pragma unroll
        for (int o=16;o;o>>=1) acc += __shfl_xor_sync(~0u, acc, o);
        if (lane==0) g_GRAM[(b*T_+t)*T_ + r] = acc;
    }
}

// ---------------- precompute: P1 = w1_0 @ xn ----------------
__global__ void k_p1(const float* __restrict__ w1)
{
    int hc = blockIdx.x;
    int b  = blockIdx.y;
    int tid = threadIdx.x, lane = tid&31, w = tid>>5;
    __shared__ float xns[32][D_];
    for (int half = 0; half < 2; half++) {
        for (int idx = tid; idx < 32*D_; idx += NT) {
            int tt = idx / D_, d = idx % D_;
            xns[tt][d] = g_XN[(b*T_ + half*32 + tt)*D_ + d];
        }
        __syncthreads();
        for (int j = 0; j < 8; j++) {
            int h = hc*64 + w*8 + j;
            float wr[8];
            #pragma unroll
            for (int k=0;k<8;k++) wr[k] = w1[h*D_ + lane + 32*k];
            for (int tt = 0; tt < 32; tt++) {
                float acc = 0.f;
                #pragma unroll
                for (int k=0;k<8;k++) acc += wr[k]*xns[tt][lane + 32*k];
                #pragma unroll
                for (int o=16;o;o>>=1) acc += __shfl_xor_sync(~0u, acc, o);
                if (lane==0) g_P1[(b*T_ + half*32 + tt)*H_ + h] = acc;
            }
        }
        __syncthreads();
    }
}

// ---------------- main kernel: cluster of 8 CTAs per batch ----------------
__global__ __launch_bounds__(NT, 1) __cluster_dims__(CPB, 1, 1)
void k_main(const float* __restrict__ values, const float* __restrict__ w2,
            float* __restrict__ out_preds, float* __restrict__ out_surp)
{
    extern __shared__ float sm[];
    float* w2s  = sm;                        // [SLICE][D_+1]  fp32 w2 slice
    float* B2s  = w2s  + SLICE*(D_+1);       // [T_][SLICE+1]  h history (fp32)
    float* h_s  = B2s  + T_*(SLICE+1);       // [SLICE]
    float* gp_s = h_s  + SLICE;              // [SLICE]
    float* dp_s = gp_s + SLICE;              // [D_]
    float* red_s= dp_s + D_;                 // [D_+T_+1]
    float* cf_s = red_s+ (D_+T_+1);          // [T_] forward coefs (next step)
    float* cf2  = cf_s + T_;                 // [T_] Pc*v
    float* cfu  = cf2  + T_;                 // [T_] Pc*u
    float* Pc   = cfu  + T_;                 // [T_]
    float* Mc   = Pc   + T_;                 // [T_]
    float* fxp  = Mc   + T_;                 // [2][SLICE]
    float* rs   = fxp  + 2*SLICE;            // [8] hh2 warp partials
    float* rs2  = rs   + 8;                  // [8] dn2
    float* rs3  = rs2  + 8;                  // [8] gn2
    float* sc   = rs3  + 8;                  // 0=alpha 3=clip 4=G[t][t]
    __nv_bfloat16* A1h = (__nv_bfloat16*)(sc + 8);          // [T_][SLICE] dh history
    __nv_bfloat16* A2h = A1h + T_*SLICE;                    // [T_][D_]    dp history

    int tid = threadIdx.x, lane = tid&31, wid = tid>>5;
    int b     = blockIdx.x / CPB;
    int crank = blockIdx.x % CPB;
    int base  = crank * SLICE;

    // stage w2 slice (transposed, pad-257 -> conflict-free both directions)
    for (int idx = tid; idx < D_*SLICE; idx += NT) {
        int d = idx >> 7, il = idx & (SLICE-1);
        w2s[il*(D_+1) + d] = w2[d*H_ + base + il];
    }
    if (tid < T_) { Pc[tid] = 0.f; Mc[tid] = 0.f; }
    if (tid == 0) { sc[0] = 1.0f; sc[4] = g_GRAM[(b*T_)*T_]; }

    float a2[T_];                 // per-thread dp history for column d=tid
    #pragma unroll
    for (int r=0;r<T_;r++) a2[r] = 0.f;

    // prefetch step-0 operands
    float p1v = (tid < SLICE) ? g_P1[(b*T_)*H_ + base + tid] : 0.f;
    float vv  = values[(b*T_)*D_ + tid];
    __syncthreads();

    for (int t = 0; t < T_; t++) {
        float alpha = sc[0];
        float gtt   = sc[4];

        // ---- phase 2: h slice = gelu(alpha*P1 + A1 @ cf) ----
        float hh2 = 0.f;
        if (tid < SLICE) {
            float z = alpha * p1v;
            #pragma unroll 8
            for (int r=0;r<t;r++) z += cf_s[r]*__bfloat162float(A1h[r*SLICE + tid]);
            float ph = 0.5f*(1.0f + erff(z*0.70710678118654752f));
            float h  = z*ph;
            float gp = ph + z*0.39894228040143268f*expf(-0.5f*z*z);
            h_s[tid] = h; gp_s[tid] = gp;
            B2s[t*(SLICE+1) + tid] = h;
            hh2 = h*h;
        }
        #pragma unroll
        for (int o=16;o;o>>=1) hh2 += __shfl_xor_sync(~0u, hh2, o);
        if (lane==0) rs[wid] = hh2;
        __syncthreads();

        // ---- phase 3a: partial pred + partial v_r + hn2 partial ----
        {
            float acc = 0.f;
            #pragma unroll 8
            for (int i=0;i<SLICE;i++) acc += w2s[i*(D_+1)+tid]*h_s[i];
            g_RED1[b][crank][tid] = acc;
        }
        for (int rr = wid; rr < t; rr += 8) {
            float acc = 0.f;
            #pragma unroll
            for (int k=0;k<4;k++) acc += B2s[rr*(SLICE+1) + lane + 32*k]*h_s[lane + 32*k];
            #pragma unroll
            for (int o=16;o;o>>=1) acc += __shfl_xor_sync(~0u, acc, o);
            if (lane==0) g_RED1[b][crank][D_+rr] = acc;
        }
        if (tid==0) {
            float s=0.f;
            #pragma unroll
            for (int i=0;i<8;i++) s += rs[i];
            g_RED1[b][crank][D_+T_] = s;
        }
        CLUSTER_SYNC();

        // prefetch next-step operands (hidden under 3b/4)
        float gr_next = 0.f, p1n = 0.f, vn = 0.f;
        if (t+1 < T_) {
            if (tid <= t+1) gr_next = g_GRAM[(b*T_+t+1)*T_ + tid];
            if (tid < SLICE) p1n = g_P1[(b*T_+t+1)*H_ + base + tid];
            vn = values[(b*T_+t+1)*D_ + tid];
        }

        // ---- phase 3b: reduce partials; fold cf2 ----
        {
            float s = 0.f;
            #pragma unroll
            for (int j=0;j<CPB;j++) s += g_RED1[b][j][tid];
            red_s[tid] = s;
            if (tid < D_+T_+1-D_) {          // tid < 65 handles k = 256..320
                int k2 = D_ + tid;
                float s2 = 0.f;
                #pragma unroll
                for (int j=0;j<CPB;j++) s2 += g_RED1[b][j][k2];
                red_s[k2] = s2;
                if (tid < T_) cf2[tid] = Pc[tid]*s2;   // Pc[r]*v_r
            }
        }
        __syncthreads();

        // ---- pred via register history, dp, dn2 ----
        {
            float pr = alpha * red_s[tid];
            #pragma unroll
            for (int r=0;r<T_;r++) if (r<t) pr += cf2[r]*a2[r];
            float dp = 2.0f*(pr - vv);
            dp_s[tid] = dp;
            A2h[t*D_ + tid] = __float2bfloat16(dp);
            #pragma unroll
            for (int r=0;r<T_;r++) if (r==t) a2[r] = dp;
            if (crank==0) out_preds[(b*T_+t)*D_ + tid] = pr;
            float dn2p = dp*dp;
            #pragma unroll
            for (int o=16;o;o>>=1) dn2p += __shfl_xor_sync(~0u, dn2p, o);
            if (lane==0) rs2[wid] = dn2p;
        }
        __syncthreads();

        // ---- u[r] = A2[r].dp via warp-per-rank smem dots (bf16x2) ----
        for (int rr = wid; rr < t; rr += 8) {
            const uint32_t* row = (const uint32_t*)(A2h + rr*D_);
            float acc = 0.f;
            #pragma unroll
            for (int k=0;k<4;k++) {
                uint32_t pk = row[lane + 32*k];
                __nv_bfloat162 v2 = *(__nv_bfloat162*)&pk;
                int d0 = 2*(lane + 32*k);
                acc += __bfloat162float(v2.x)*dp_s[d0] + __bfloat162float(v2.y)*dp_s[d0+1];
            }
            #pragma unroll
            for (int o=16;o;o>>=1) acc += __shfl_xor_sync(~0u, acc, o);
            if (lane==0) cfu[rr] = Pc[rr]*acc;
        }
        __syncthreads();

        // ---- phase 4: fx = w2s . dp (split over 256 threads) ----
        {
            int i = tid & (SLICE-1), hf = tid >> 7;
            const float* wrow = w2s + i*(D_+1) + hf*128;
            const float* dpp  = dp_s + hf*128;
            float acc = 0.f;
            #pragma unroll 8
            for (int d=0; d<128; d++) acc += wrow[d]*dpp[d];
            fxp[hf*SLICE + i] = acc;
        }
        __syncthreads();
        float gn2 = 0.f;
        if (tid < SLICE) {
            float dh = alpha*(fxp[tid] + fxp[SLICE+tid]);
            #pragma unroll 8
            for (int r=0;r<t;r++) dh += cfu[r]*B2s[r*(SLICE+1)+tid];
            float dhp = dh * gp_s[tid];
            A1h[t*SLICE + tid] = __float2bfloat16(dhp);
            gn2 = dhp*dhp;
        }
        #pragma unroll
        for (int o=16;o;o>>=1) gn2 += __shfl_xor_sync(~0u, gn2, o);
        if (lane==0) rs3[wid] = gn2;
        __syncthreads();
        if (tid==0) {
            float s=0.f;
            #pragma unroll
            for (int i=0;i<8;i++) s += rs3[i];
            g_RED2[b][crank] = s;
        }
        CLUSTER_SYNC();

        // ---- phase 5: gnorm, clip, coefficient recurrences ----
        if (tid==0) {
            float dhn2 = 0.f;
            #pragma unroll
            for (int j=0;j<CPB;j++) dhn2 += g_RED2[b][j];
            float dn2 = 0.f;
            #pragma unroll
            for (int i=0;i<8;i++) dn2 += rs2[i];
            float gn = sqrtf(dhn2*gtt + dn2*red_s[D_+T_]);
            sc[3] = fminf(1.0f/(gn + EPS_), 1.0f);
            if (crank==0) out_surp[b*T_ + t] = gn;
            sc[0] = alpha*(1.0f - DECAY);
        }
        __syncthreads();
        {
            float clip = sc[3];
            if (tid < t) {
                float m = Mc[tid]*MU;
                Mc[tid] = m;
                float p = Pc[tid]*(1.0f - DECAY) - LR*m;
                Pc[tid] = p;
                cf_s[tid] = p*gr_next;
            } else if (tid == t) {
                Mc[t] = clip;
                float p = -LR*clip;
                Pc[t] = p;
                cf_s[t] = p*gr_next;
            } else if (tid == t+1 && t+1 < T_) {
                sc[4] = gr_next;
            }
        }
        p1v = p1n; vv = vn;
        __syncthreads();
    }
}

// ---------------- launch ----------------
extern "C" void kernel_launch(void* const* d_in, const int* in_sizes, int n_in,
                              void* d_out, int out_size)
{
    (void)in_sizes; (void)n_in; (void)out_size;
    const float* keys   = (const float*)d_in[0];
    const float* values = (const float*)d_in[1];
    const float* w1     = (const float*)d_in[2];
    const float* w2     = (const float*)d_in[3];
    float* out       = (float*)d_out;
    float* out_preds = out;                 // [B,T,D]
    float* out_surp  = out + B_*T_*D_;      // [B,T]

    k_norm<<<B_*T_, D_>>>(keys);
    k_gram<<<B_*T_, 256>>>();
    dim3 gp1(H_/64, B_);
    k_p1<<<gp1, NT>>>(w1);

    const size_t f32_cnt =
        (size_t)SLICE*(D_+1) + (size_t)T_*(SLICE+1)
        + SLICE + SLICE + D_ + (D_+T_+1) + 5*T_ + 2*SLICE + 32;
    const size_t smem_bytes = f32_cnt*sizeof(float)
        + (size_t)(T_*SLICE + T_*D_)*sizeof(__nv_bfloat16);
    cudaFuncSetAttribute(k_main, cudaFuncAttributeMaxDynamicSharedMemorySize,
                         (int)smem_bytes);
    k_main<<<B_*CPB, NT, smem_bytes>>>(values, w2, out_preds, out_surp);
}

// round 3
// speedup vs baseline: 1.4142x; 1.1172x over previous
#include <cuda_runtime.h>
#include <cuda_bf16.h>
#include <cstdint>

// ---------------- problem constants ----------------
#define B_  8
#define T_  64
#define D_  256
#define H_  1024
#define CPB 8            // CTAs per batch (cluster size)
#define SLICE 128        // H rows per CTA
#define NT  512
#define LR    1e-3f
#define DECAY 0.02f
#define MU    0.9f
#define EPS_  1e-6f

#define CLUSTER_SYNC() do { \
    asm volatile("barrier.cluster.arrive.aligned;" ::: "memory"); \
    asm volatile("barrier.cluster.wait.aligned;"  ::: "memory"); } while (0)

// ---------------- device scratch ----------------
__device__ float g_XN[B_*T_*D_];
__device__ float g_GRAM[B_*T_*T_];
__device__ float g_P1[B_*T_*H_];
__device__ float g_RED1[B_][CPB][2][D_+T_+1];

// DSMEM store helper: write v into CTA `rank`'s smem at the same offset as laddr
__device__ __forceinline__ void dsmem_st(uint32_t laddr, int rank, float v)
{
    uint32_t ra;
    asm volatile("mapa.shared::cluster.u32 %0, %1, %2;" : "=r"(ra) : "r"(laddr), "r"(rank));
    asm volatile("st.shared::cluster.b32 [%0], %1;" :: "r"(ra), "r"(__float_as_uint(v)) : "memory");
}

// ---------------- precompute: normalize keys ----------------
__global__ void k_norm(const float* __restrict__ keys)
{
    int bt = blockIdx.x, tid = threadIdx.x;
    float v = keys[bt*D_ + tid];
    float ss = v*v;
    #pragma unroll
    for (int o=16;o;o>>=1) ss += __shfl_xor_sync(~0u, ss, o);
    __shared__ float ws[8];
    __shared__ float s_scale;
    if ((tid&31)==0) ws[tid>>5] = ss;
    __syncthreads();
    if (tid==0) {
        float tot=0.f;
        #pragma unroll
        for (int i=0;i<8;i++) tot += ws[i];
        s_scale = 1.0f / fmaxf(sqrtf(tot), 1e-12f);
    }
    __syncthreads();
    g_XN[bt*D_ + tid] = v * s_scale;
}

// ---------------- precompute: Gram matrix ----------------
__global__ void k_gram()
{
    int bt = blockIdx.x, b = bt / T_, t = bt % T_;
    int tid = threadIdx.x, lane = tid&31, w = tid>>5;
    __shared__ float xt[D_];
    xt[tid] = g_XN[bt*D_ + tid];
    __syncthreads();
    for (int r = w; r < T_; r += 8) {
        const float* xr = &g_XN[(b*T_+r)*D_];
        float acc = 0.f;
        #pragma unroll
        for (int k=lane; k<D_; k+=32) acc += xr[k]*xt[k];
        #pragma unroll
        for (int o=16;o;o>>=1) acc += __shfl_xor_sync(~0u, acc, o);
        if (lane==0) g_GRAM[(b*T_+t)*T_ + r] = acc;
    }
}

// ---------------- precompute: P1 = w1_0 @ xn ----------------
__global__ void k_p1(const float* __restrict__ w1)
{
    int hc = blockIdx.x;
    int b  = blockIdx.y;
    int tid = threadIdx.x, lane = tid&31, w = tid>>5;
    __shared__ float xns[32][D_];
    for (int half = 0; half < 2; half++) {
        for (int idx = tid; idx < 32*D_; idx += 256) {
            int tt = idx / D_, d = idx % D_;
            xns[tt][d] = g_XN[(b*T_ + half*32 + tt)*D_ + d];
        }
        __syncthreads();
        for (int j = 0; j < 8; j++) {
            int h = hc*64 + w*8 + j;
            float wr[8];
            #pragma unroll
            for (int k=0;k<8;k++) wr[k] = w1[h*D_ + lane + 32*k];
            for (int tt = 0; tt < 32; tt++) {
                float acc = 0.f;
                #pragma unroll
                for (int k=0;k<8;k++) acc += wr[k]*xns[tt][lane + 32*k];
                #pragma unroll
                for (int o=16;o;o>>=1) acc += __shfl_xor_sync(~0u, acc, o);
                if (lane==0) g_P1[(b*T_ + half*32 + tt)*H_ + h] = acc;
            }
        }
        __syncthreads();
    }
}

// ---------------- main kernel: cluster of 8 CTAs per batch, 512 threads ----------------
__global__ __launch_bounds__(NT, 1) __cluster_dims__(CPB, 1, 1)
void k_main(const float* __restrict__ values, const float* __restrict__ w2,
            float* __restrict__ out_preds, float* __restrict__ out_surp)
{
    extern __shared__ float sm[];
    float* w2s  = sm;                        // [SLICE][D_+1]
    float* B2s  = w2s  + SLICE*(D_+1);       // [T_][SLICE+1]  h history
    float* h_s  = B2s  + T_*(SLICE+1);       // [SLICE]
    float* gp_s = h_s  + SLICE;              // [SLICE]
    float* dp_s = gp_s + SLICE;              // [D_]   (8B aligned)
    float* red_s= dp_s + D_;                 // [322]
    float* cf_s = red_s+ 322;                // [T_]
    float* cf2  = cf_s + T_;                 // [T_]
    float* cfu  = cf2  + T_;                 // [T_]
    float* Pc   = cfu  + T_;                 // [T_]
    float* Mc   = Pc   + T_;                 // [T_]
    float* zp   = Mc   + T_;                 // [4][SLICE]
    float* predp= zp   + 4*SLICE;            // [D_]
    float* rs   = predp+ D_;                 // [8] hh2 partials (4 used)
    float* rs2  = rs   + 8;                  // [8] dn2 partials
    float* rs3  = rs2  + 8;                  // [8] gn2 partials (4 used)
    float* gred = rs3  + 8;                  // [8] gn2 per-CTA (DSMEM filled)
    float* sc   = gred + 8;                  // 0=alpha 3=clip 4=G[t][t]
    __nv_bfloat16* A1h = (__nv_bfloat16*)(sc + 8);   // [T_][SLICE]
    __nv_bfloat16* A2h = A1h + T_*SLICE;             // [T_][D_]

    int tid = threadIdx.x, lane = tid&31, wid = tid>>5;
    int b     = blockIdx.x / CPB;
    int crank = blockIdx.x % CPB;
    int base  = crank * SLICE;

    // stage w2 slice (transposed, pad-257 -> conflict-free rows and columns)
    for (int idx = tid; idx < D_*SLICE; idx += NT) {
        int d = idx >> 7, il = idx & (SLICE-1);
        w2s[il*(D_+1) + d] = w2[d*H_ + base + il];
    }
    if (tid < T_) { Pc[tid] = 0.f; Mc[tid] = 0.f; }
    if (tid <= T_) g_RED1[b][crank][1][D_+tid] = 0.f;   // unwritten slots must be 0
    if (tid == 0) { sc[0] = 1.0f; sc[4] = g_GRAM[(b*T_)*T_]; }

    // per-thread dpred history registers, split across halves
    float a2[32];
    #pragma unroll
    for (int r=0;r<32;r++) a2[r] = 0.f;

    // step-0 prefetches
    float p1v = (tid < SLICE) ? g_P1[(b*T_)*H_ + base + tid] : 0.f;
    float vv  = (tid < D_)    ? values[(b*T_)*D_ + tid] : 0.f;
    __syncthreads();

    for (int t = 0; t < T_; t++) {
        float alpha = sc[0];
        float gtt   = sc[4];

        // ---- phase 2: z = alpha*P1 + A1 @ cf, split 4-way over r ----
        {
            int g = tid >> 7, i = tid & 127;
            float z = (g==0) ? alpha * p1v : 0.f;
            for (int r=g; r<t; r+=4) z += cf_s[r]*__bfloat162float(A1h[r*SLICE + i]);
            zp[g*SLICE + i] = z;
        }
        __syncthreads();
        if (tid < SLICE) {
            float z = zp[tid] + zp[SLICE+tid] + zp[2*SLICE+tid] + zp[3*SLICE+tid];
            float ph = 0.5f*(1.0f + erff(z*0.70710678118654752f));
            float h  = z*ph;
            float gp = ph + z*0.39894228040143268f*expf(-0.5f*z*z);
            h_s[tid] = h; gp_s[tid] = gp;
            B2s[t*(SLICE+1) + tid] = h;
            float hh2 = h*h;
            #pragma unroll
            for (int o=16;o;o>>=1) hh2 += __shfl_xor_sync(~0u, hh2, o);
            if (lane==0) rs[wid] = hh2;
        }
        __syncthreads();

        // ---- phase 3a: pred partials (split-i), v_r dots, hn2 ----
        {
            int d = tid & 255, hf = tid >> 8;
            const float* col = w2s + (hf*64)*(D_+1) + d;
            float a0=0.f, a1=0.f;
            #pragma unroll
            for (int ii=0; ii<64; ii+=2) {
                a0 += col[ ii   *(D_+1)] * h_s[hf*64+ii];
                a1 += col[(ii+1)*(D_+1)] * h_s[hf*64+ii+1];
            }
            g_RED1[b][crank][hf][d] = a0 + a1;
        }
        for (int rr = wid; rr < t; rr += 16) {
            float acc = 0.f;
            #pragma unroll
            for (int k=0;k<4;k++) acc += B2s[rr*(SLICE+1) + lane + 32*k]*h_s[lane + 32*k];
            #pragma unroll
            for (int o=16;o;o>>=1) acc += __shfl_xor_sync(~0u, acc, o);
            if (lane==0) g_RED1[b][crank][0][D_+rr] = acc;
        }
        if (tid==0) g_RED1[b][crank][0][D_+T_] = rs[0]+rs[1]+rs[2]+rs[3];
        CLUSTER_SYNC();

        // next-step prefetch (hidden under reduce/pred)
        float gr_next = 0.f, p1n = 0.f, vn = 0.f;
        if (t+1 < T_) {
            if (tid <= t+1)   gr_next = g_GRAM[(b*T_+t+1)*T_ + tid];
            if (tid < SLICE)  p1n = g_P1[(b*T_+t+1)*H_ + base + tid];
            if (tid < D_)     vn  = values[(b*T_+t+1)*D_ + tid];
        }

        // ---- phase 3b: cross-cluster reduce ----
        if (tid < D_+T_+1) {
            float s = 0.f;
            #pragma unroll
            for (int j=0;j<CPB;j++) s += g_RED1[b][j][0][tid] + g_RED1[b][j][1][tid];
            red_s[tid] = s;
            if (tid >= D_ && tid < D_+T_) cf2[tid-D_] = Pc[tid-D_]*s;
        }
        __syncthreads();

        // ---- pred via split register history ----
        float pr = 0.f;
        if (tid < D_) {
            pr = alpha * red_s[tid];
            #pragma unroll
            for (int r=0;r<32;r++) if (r<t) pr += cf2[r]*a2[r];
        } else {
            int d = tid - D_;
            float ph2 = 0.f;
            #pragma unroll
            for (int r=32;r<T_;r++) if (r<t) ph2 += cf2[r]*a2[r-32];
            predp[d] = ph2;
        }
        __syncthreads();
        if (tid < D_) {
            pr += predp[tid];
            float dp = 2.0f*(pr - vv);
            dp_s[tid] = dp;
            A2h[t*D_ + tid] = __float2bfloat16(dp);
            if (t < 32) a2[t] = dp;
            if (crank==0) out_preds[(b*T_+t)*D_ + tid] = pr;
            float dn2p = dp*dp;
            #pragma unroll
            for (int o=16;o;o>>=1) dn2p += __shfl_xor_sync(~0u, dn2p, o);
            if (lane==0) rs2[wid] = dn2p;
        }
        __syncthreads();

        // ---- u[r] = A2[r].dp (warp-per-rank, bf16x2 + float2) ----
        for (int rr = wid; rr < t; rr += 16) {
            const uint32_t* row = (const uint32_t*)(A2h + rr*D_);
            const float2*   dp2 = (const float2*)dp_s;
            float acc = 0.f;
            #pragma unroll
            for (int k=0;k<4;k++) {
                uint32_t pk = row[lane + 32*k];
                __nv_bfloat162 v2 = *(__nv_bfloat162*)&pk;
                float2 dv = dp2[lane + 32*k];
                acc += __bfloat162float(v2.x)*dv.x + __bfloat162float(v2.y)*dv.y;
            }
            #pragma unroll
            for (int o=16;o;o>>=1) acc += __shfl_xor_sync(~0u, acc, o);
            if (lane==0) cfu[rr] = Pc[rr]*acc;
        }
        if (tid >= D_ && t >= 32) a2[t-32] = dp_s[tid-D_];   // high-half history update
        __syncthreads();

        // ---- phase 4: dh partials = alpha*(w2 row dot over d-quarter) + rank(r mod 4) ----
        {
            int q = tid >> 7, i = tid & 127;
            const float* wrow = w2s + i*(D_+1) + q*64;
            const float* dpp  = dp_s + q*64;
            float a0=0.f, a1=0.f;
            #pragma unroll
            for (int d=0; d<64; d+=2) { a0 += wrow[d]*dpp[d]; a1 += wrow[d+1]*dpp[d+1]; }
            float acc = alpha*(a0+a1);
            for (int r=q; r<t; r+=4) acc += cfu[r]*B2s[r*(SLICE+1)+i];
            zp[q*SLICE + i] = acc;
        }
        __syncthreads();
        if (tid < SLICE) {
            float dh = zp[tid] + zp[SLICE+tid] + zp[2*SLICE+tid] + zp[3*SLICE+tid];
            float dhp = dh * gp_s[tid];
            A1h[t*SLICE + tid] = __float2bfloat16(dhp);
            float gn2 = dhp*dhp;
            #pragma unroll
            for (int o=16;o;o>>=1) gn2 += __shfl_xor_sync(~0u, gn2, o);
            if (lane==0) rs3[wid] = gn2;
        }
        __syncthreads();

        // ---- broadcast gn2 partial to all CTAs via DSMEM, then cluster barrier ----
        if (wid==0) {
            float v = (lane<4) ? rs3[lane] : 0.f;
            #pragma unroll
            for (int o=16;o;o>>=1) v += __shfl_xor_sync(~0u, v, o);
            if (lane < CPB) {
                uint32_t la = (uint32_t)__cvta_generic_to_shared(&gred[crank]);
                dsmem_st(la, lane, v);
            }
        }
        CLUSTER_SYNC();

        // ---- phase 5: gnorm, clip (warp 0, all local) ----
        if (wid==0) {
            float a = (lane<CPB) ? gred[lane] : 0.f;   // sum dh'^2 across cluster
            float c = (lane<8)   ? rs2[lane]  : 0.f;   // dn2 partials (local, replicated)
            #pragma unroll
            for (int o=16;o;o>>=1) { a += __shfl_xor_sync(~0u, a, o);
                                     c += __shfl_xor_sync(~0u, c, o); }
            if (lane==0) {
                float gn = sqrtf(a*gtt + c*red_s[D_+T_]);
                sc[3] = fminf(1.0f/(gn + EPS_), 1.0f);
                sc[0] = alpha*(1.0f - DECAY);
                if (crank==0) out_surp[b*T_ + t] = gn;
            }
        }
        __syncthreads();
        {
            float clip = sc[3];
            if (tid < t) {
                float m = Mc[tid]*MU;
                Mc[tid] = m;
                float p = Pc[tid]*(1.0f - DECAY) - LR*m;
                Pc[tid] = p;
                cf_s[tid] = p*gr_next;
            } else if (tid == t) {
                Mc[t] = clip;
                float p = -LR*clip;
                Pc[t] = p;
                cf_s[t] = p*gr_next;
            } else if (tid == t+1 && t+1 < T_) {
                sc[4] = gr_next;
            }
        }
        p1v = p1n; vv = vn;
        __syncthreads();
    }
}

// ---------------- launch ----------------
extern "C" void kernel_launch(void* const* d_in, const int* in_sizes, int n_in,
                              void* d_out, int out_size)
{
    (void)in_sizes; (void)n_in; (void)out_size;
    const float* keys   = (const float*)d_in[0];
    const float* values = (const float*)d_in[1];
    const float* w1     = (const float*)d_in[2];
    const float* w2     = (const float*)d_in[3];
    float* out       = (float*)d_out;
    float* out_preds = out;                 // [B,T,D]
    float* out_surp  = out + B_*T_*D_;      // [B,T]

    k_norm<<<B_*T_, D_>>>(keys);
    k_gram<<<B_*T_, 256>>>();
    dim3 gp1(H_/64, B_);
    k_p1<<<gp1, 256>>>(w1);

    const size_t f32_cnt =
        (size_t)SLICE*(D_+1) + (size_t)T_*(SLICE+1)
        + SLICE + SLICE + D_ + 322 + 5*T_ + 4*SLICE + D_ + 8+8+8+8+8;
    const size_t smem_bytes = f32_cnt*sizeof(float)
        + (size_t)(T_*SLICE + T_*D_)*sizeof(__nv_bfloat16);
    cudaFuncSetAttribute(k_main, cudaFuncAttributeMaxDynamicSharedMemorySize,
                         (int)smem_bytes);
    k_main<<<B_*CPB, NT, smem_bytes>>>(values, w2, out_preds, out_surp);
}

// round 4
// speedup vs baseline: 1.8997x; 1.3433x over previous
#include <cuda_runtime.h>
#include <cstdint>

// ---------------- problem constants ----------------
#define B_  8
#define T_  64
#define D_  256
#define H_  1024
#define CPB 8            // CTAs per batch (cluster size)
#define SLICE 128        // H rows per CTA
#define NT  512
#define LR    1e-3f
#define DECAY 0.02f
#define MU    0.9f
#define EPS_  1e-6f

#define CLUSTER_SYNC() do { \
    asm volatile("barrier.cluster.arrive.aligned;" ::: "memory"); \
    asm volatile("barrier.cluster.wait.aligned;"  ::: "memory"); } while (0)
#define CLUSTER_ARRIVE() asm volatile("barrier.cluster.arrive.aligned;" ::: "memory")
#define CLUSTER_WAIT()   asm volatile("barrier.cluster.wait.aligned;"  ::: "memory")

// ---------------- device scratch ----------------
__device__ float g_XN[B_*T_*D_];
__device__ float g_GRAM[B_*T_*T_];
__device__ float g_P1[B_*T_*H_];
__device__ float g_RED1[B_][CPB][324];   // [0:256) pred, [256:320) v_r, [320] hn2

__device__ __forceinline__ void dsmem_st(uint32_t laddr, int rank, float v)
{
    uint32_t ra;
    asm volatile("mapa.shared::cluster.u32 %0, %1, %2;" : "=r"(ra) : "r"(laddr), "r"(rank));
    asm volatile("st.shared::cluster.b32 [%0], %1;" :: "r"(ra), "r"(__float_as_uint(v)) : "memory");
}

// ---------------- precompute: normalize keys ----------------
__global__ void k_norm(const float* __restrict__ keys)
{
    int bt = blockIdx.x, tid = threadIdx.x;
    float v = keys[bt*D_ + tid];
    float ss = v*v;
    #pragma unroll
    for (int o=16;o;o>>=1) ss += __shfl_xor_sync(~0u, ss, o);
    __shared__ float ws[8];
    __shared__ float s_scale;
    if ((tid&31)==0) ws[tid>>5] = ss;
    __syncthreads();
    if (tid==0) {
        float tot=0.f;
        #pragma unroll
        for (int i=0;i<8;i++) tot += ws[i];
        s_scale = 1.0f / fmaxf(sqrtf(tot), 1e-12f);
    }
    __syncthreads();
    g_XN[bt*D_ + tid] = v * s_scale;
}

// ---------------- precompute: Gram matrix ----------------
__global__ void k_gram()
{
    int bt = blockIdx.x, b = bt / T_, t = bt % T_;
    int tid = threadIdx.x, lane = tid&31, w = tid>>5;
    __shared__ float xt[D_];
    xt[tid] = g_XN[bt*D_ + tid];
    __syncthreads();
    for (int r = w; r < T_; r += 8) {
        const float* xr = &g_XN[(b*T_+r)*D_];
        float acc = 0.f;
        #pragma unroll
        for (int k=lane; k<D_; k+=32) acc += xr[k]*xt[k];
        #pragma unroll
        for (int o=16;o;o>>=1) acc += __shfl_xor_sync(~0u, acc, o);
        if (lane==0) g_GRAM[(b*T_+t)*T_ + r] = acc;
    }
}

// ---------------- precompute: P1 = w1_0 @ xn ----------------
__global__ void k_p1(const float* __restrict__ w1)
{
    int hc = blockIdx.x;   // 32 chunks of 32 H-rows
    int b  = blockIdx.y;
    int tid = threadIdx.x, lane = tid&31, w = tid>>5;
    __shared__ float xns[32][D_];
    for (int half = 0; half < 2; half++) {
        for (int idx = tid; idx < 32*D_; idx += 256) {
            int tt = idx / D_, d = idx % D_;
            xns[tt][d] = g_XN[(b*T_ + half*32 + tt)*D_ + d];
        }
        __syncthreads();
        for (int j = 0; j < 4; j++) {
            int h = hc*32 + w*4 + j;
            float wr[8];
            #pragma unroll
            for (int k=0;k<8;k++) wr[k] = w1[h*D_ + lane + 32*k];
            for (int tt = 0; tt < 32; tt++) {
                float acc = 0.f;
                #pragma unroll
                for (int k=0;k<8;k++) acc += wr[k]*xns[tt][lane + 32*k];
                #pragma unroll
                for (int o=16;o;o>>=1) acc += __shfl_xor_sync(~0u, acc, o);
                if (lane==0) g_P1[(b*T_ + half*32 + tt)*H_ + h] = acc;
            }
        }
        __syncthreads();
    }
}

// ---------------- main kernel ----------------
__global__ __launch_bounds__(NT, 1) __cluster_dims__(CPB, 1, 1)
void k_main(const float* __restrict__ values, const float* __restrict__ w2,
            float* __restrict__ out_preds, float* __restrict__ out_surp)
{
    extern __shared__ float sm[];
    float* B2s  = sm;                        // [64][132] h history
    float* A1f  = B2s  + 64*132;             // [64][132] dh' history (fp32)
    float* A2f  = A1f  + 64*132;             // [64][264] dpred history (fp32)
    float* fxr  = A2f  + 64*264;             // [16][132] backward-dot warp partials
    float* zp   = fxr  + 16*132;             // [4][128]
    float* h_s  = zp   + 512;                // [128]
    float* gp_s = h_s  + 128;                // [128]
    float* dp_s = gp_s + 128;                // [256]
    float* red_s= dp_s + 256;                // [324]
    float* predp= red_s+ 324;                // [256]
    float* cf2  = predp+ 256;                // [64]
    float* cfu  = cf2  + 64;                 // [64]
    float* cf_s = cfu  + 64;                 // [64]
    float* Pc   = cf_s + 64;                 // [64]
    float* Mc   = Pc   + 64;                 // [64]
    float* gr_s = Mc   + 64;                 // [68] next Gram row
    float* rs   = gr_s + 68;                 // [8] hn2 partials (4 used)
    float* rs2  = rs   + 8;                  // [8] dn2 partials
    float* rs3  = rs2  + 8;                  // [8] gn2 partials (4 used)
    float* gred = rs3  + 8;                  // [8] per-CTA gn2 (DSMEM)
    float* sc   = gred + 8;                  // 0=alpha 5=cf_t

    const int tid = threadIdx.x, lane = tid&31, wid = tid>>5;
    const int ti = tid & 15, td = tid >> 4;
    const int b     = blockIdx.x / CPB;
    const int crank = blockIdx.x % CPB;
    const int base  = crank * SLICE;

    // ---- register-resident w2 tile: w2r[jd][ji] = w2[td*8+jd][base + ti*8+ji]
    float w2r[8][8];
    {
        const float* wbase = w2 + base + ti*8;
        #pragma unroll
        for (int jd=0;jd<8;jd++) {
            const float4* p = (const float4*)(wbase + (td*8+jd)*(size_t)H_);
            float4 x = p[0], y = p[1];
            w2r[jd][0]=x.x; w2r[jd][1]=x.y; w2r[jd][2]=x.z; w2r[jd][3]=x.w;
            w2r[jd][4]=y.x; w2r[jd][5]=y.y; w2r[jd][6]=y.z; w2r[jd][7]=y.w;
        }
    }
    if (tid==0) sc[0] = 1.0f;

    // ---- pre-loop: h_0 = gelu(P1_0)
    if (tid < SLICE) {
        float z = g_P1[(b*T_)*H_ + base + tid];
        float ph = 0.5f*(1.0f + erff(z*0.70710678118654752f));
        float h  = z*ph;
        float gp = ph + z*0.39894228040143268f*expf(-0.5f*z*z);
        h_s[tid] = h; gp_s[tid] = gp; B2s[tid] = h;
        float hh2 = h*h;
        #pragma unroll
        for (int o=16;o;o>>=1) hh2 += __shfl_xor_sync(~0u, hh2, o);
        if (lane==0) rs[wid] = hh2;
    }
    float vv  = (tid < D_) ? values[(b*T_)*D_ + tid] : 0.f;
    __syncthreads();

    for (int t = 0; t < T_; t++) {
        const float alpha = sc[0];

        // ---- (A) pred partials via registers + shfl; v_r dots; hn2 ----
        {
            float4 hv0 = *(const float4*)&h_s[ti*8];
            float4 hv1 = *(const float4*)&h_s[ti*8+4];
            float hb[8] = {hv0.x,hv0.y,hv0.z,hv0.w,hv1.x,hv1.y,hv1.z,hv1.w};
            float p[8] = {0,0,0,0,0,0,0,0};
            #pragma unroll
            for (int jd=0;jd<8;jd++)
                #pragma unroll
                for (int ii=0;ii<8;ii++) p[jd] += w2r[jd][ii]*hb[ii];
            #pragma unroll
            for (int jd=0;jd<8;jd++) {
                p[jd] += __shfl_xor_sync(~0u, p[jd], 1);
                p[jd] += __shfl_xor_sync(~0u, p[jd], 2);
                p[jd] += __shfl_xor_sync(~0u, p[jd], 4);
                p[jd] += __shfl_xor_sync(~0u, p[jd], 8);
            }
            if ((lane&15)==0) {
                #pragma unroll
                for (int jd=0;jd<8;jd++) g_RED1[b][crank][td*8+jd] = p[jd];
            }
        }
        for (int rr = wid; rr < t; rr += 16) {
            float4 bv = *(const float4*)&B2s[rr*132 + lane*4];
            float4 hv = *(const float4*)&h_s[lane*4];
            float acc = bv.x*hv.x + bv.y*hv.y + bv.z*hv.z + bv.w*hv.w;
            #pragma unroll
            for (int o=16;o;o>>=1) acc += __shfl_xor_sync(~0u, acc, o);
            if (lane==0) g_RED1[b][crank][D_+rr] = acc;
        }
        if (tid==0) g_RED1[b][crank][D_+T_] = rs[0]+rs[1]+rs[2]+rs[3];
        CLUSTER_SYNC();

        // ---- (B) next-step prefetch ----
        float p1n = 0.f, vn = 0.f;
        if (t+1 < T_) {
            if (tid <= t+1) gr_s[tid] = g_GRAM[(b*T_+t+1)*T_ + tid];
            if (tid < SLICE) p1n = g_P1[(b*T_+t+1)*H_ + base + tid];
            if (tid < D_)    vn  = values[(b*T_+t+1)*D_ + tid];
        }

        // ---- (C) cross-cluster reduce ----
        if (tid < 321) {
            float s = 0.f;
            #pragma unroll
            for (int j=0;j<CPB;j++) s += g_RED1[b][j][tid];
            red_s[tid] = s;
            if (tid >= 256 && tid < 256+T_) cf2[tid-256] = Pc[tid-256]*s;
        }
        __syncthreads();

        // ---- (D) pred with smem dpred history (even/odd split) ----
        float pr = 0.f;
        if (tid < D_) {
            pr = alpha * red_s[tid];
            for (int r=0; r<t; r+=2) pr += cf2[r]*A2f[r*264 + tid];
        } else {
            int d = tid - D_;
            float ph2 = 0.f;
            for (int r=1; r<t; r+=2) ph2 += cf2[r]*A2f[r*264 + d];
            predp[d] = ph2;
        }
        __syncthreads();
        if (tid < D_) {
            pr += predp[tid];
            float dp = 2.0f*(pr - vv);
            dp_s[tid] = dp;
            A2f[t*264 + tid] = dp;
            if (crank==0) out_preds[(b*T_+t)*D_ + tid] = pr;
            float dn2p = dp*dp;
            #pragma unroll
            for (int o=16;o;o>>=1) dn2p += __shfl_xor_sync(~0u, dn2p, o);
            if (lane==0) rs2[wid] = dn2p;
        }
        __syncthreads();

        // ---- (E) u[r] = A2f[r].dp (warp-per-rank) + (F-dot) backward via registers ----
        for (int rr = wid; rr < t; rr += 16) {
            const float4* row = (const float4*)(A2f + rr*264);
            const float4* dp4 = (const float4*)dp_s;
            float4 a0 = row[lane], a1 = row[32+lane];
            float4 d0 = dp4[lane], d1 = dp4[32+lane];
            float acc = a0.x*d0.x + a0.y*d0.y + a0.z*d0.z + a0.w*d0.w
                      + a1.x*d1.x + a1.y*d1.y + a1.z*d1.z + a1.w*d1.w;
            #pragma unroll
            for (int o=16;o;o>>=1) acc += __shfl_xor_sync(~0u, acc, o);
            if (lane==0) cfu[rr] = Pc[rr]*acc;
        }
        {
            float4 dv0 = *(const float4*)&dp_s[td*8];
            float4 dv1 = *(const float4*)&dp_s[td*8+4];
            float db[8] = {dv0.x,dv0.y,dv0.z,dv0.w,dv1.x,dv1.y,dv1.z,dv1.w};
            float f[8] = {0,0,0,0,0,0,0,0};
            #pragma unroll
            for (int jd=0;jd<8;jd++)
                #pragma unroll
                for (int ji=0;ji<8;ji++) f[ji] += w2r[jd][ji]*db[jd];
            #pragma unroll
            for (int ji=0;ji<8;ji++) f[ji] += __shfl_xor_sync(~0u, f[ji], 16);
            if (lane < 16) {
                *(float4*)&fxr[wid*132 + ti*8]   = make_float4(f[0],f[1],f[2],f[3]);
                *(float4*)&fxr[wid*132 + ti*8+4] = make_float4(f[4],f[5],f[6],f[7]);
            }
        }
        __syncthreads();

        // ---- (F-combine) 4-way over warps + rank loop ----
        {
            int q = tid >> 7, i = tid & 127;
            float s = fxr[(q*4+0)*132+i] + fxr[(q*4+1)*132+i]
                    + fxr[(q*4+2)*132+i] + fxr[(q*4+3)*132+i];
            float acc = alpha * s;
            for (int r=q; r<t; r+=4) acc += cfu[r]*B2s[r*132+i];
            zp[q*128 + i] = acc;
        }
        __syncthreads();

        // ---- (F-final) dh', A1f[t], gn2 ----
        if (tid < SLICE) {
            float dh  = zp[tid] + zp[128+tid] + zp[256+tid] + zp[384+tid];
            float dhp = dh * gp_s[tid];
            A1f[t*132 + tid] = dhp;
            float gn2 = dhp*dhp;
            #pragma unroll
            for (int o=16;o;o>>=1) gn2 += __shfl_xor_sync(~0u, gn2, o);
            if (lane==0) rs3[wid] = gn2;
        }
        __syncthreads();

        // ---- (G) DSMEM gn2 push; clip-free coefficient updates ----
        if (wid==0) {
            float v = (lane<4) ? rs3[lane] : 0.f;
            #pragma unroll
            for (int o=16;o;o>>=1) v += __shfl_xor_sync(~0u, v, o);
            if (lane < CPB) {
                uint32_t la = (uint32_t)__cvta_generic_to_shared(&gred[crank]);
                dsmem_st(la, lane, v);
            }
        }
        if (tid < t) {
            float m = Mc[tid]*MU;
            Mc[tid] = m;
            float p = Pc[tid]*(1.0f - DECAY) - LR*m;
            Pc[tid] = p;
            cf_s[tid] = p * gr_s[tid];
        }
        if (tid==0) sc[0] = alpha*(1.0f - DECAY);
        __syncthreads();
        CLUSTER_ARRIVE();

        // ---- (H) partial next-z (ranks r<t) overlapped with barrier wait ----
        {
            int g = tid >> 7, i = tid & 127;
            float z = (g==0) ? (alpha*(1.0f-DECAY))*p1n : 0.f;
            for (int r=g; r<t; r+=4) z += cf_s[r]*A1f[r*132 + i];
            zp[g*128 + i] = z;
        }
        CLUSTER_WAIT();

        // ---- (I) gnorm, clip, rank-t coefficients ----
        if (wid==0) {
            float a = (lane<CPB) ? gred[lane] : 0.f;
            float c = (lane<8)   ? rs2[lane]  : 0.f;
            #pragma unroll
            for (int o=16;o;o>>=1) { a += __shfl_xor_sync(~0u, a, o);
                                     c += __shfl_xor_sync(~0u, c, o); }
            if (lane==0) {
                float gn = sqrtf(a + c*red_s[D_+T_]);   // G[t][t] == 1
                float clip = fminf(1.0f/(gn + EPS_), 1.0f);
                if (crank==0) out_surp[b*T_ + t] = gn;
                float p = -LR*clip;
                Mc[t] = clip; Pc[t] = p;
                sc[5] = (t+1<T_) ? p*gr_s[t] : 0.f;
            }
        }
        __syncthreads();

        // ---- (K) finish next h: add rank-t term, GELU ----
        if (t+1 < T_ && tid < SLICE) {
            float z = zp[tid] + zp[128+tid] + zp[256+tid] + zp[384+tid]
                    + sc[5]*A1f[t*132 + tid];
            float ph = 0.5f*(1.0f + erff(z*0.70710678118654752f));
            float h  = z*ph;
            float gp = ph + z*0.39894228040143268f*expf(-0.5f*z*z);
            h_s[tid] = h; gp_s[tid] = gp;
            B2s[(t+1)*132 + tid] = h;
            float hh2 = h*h;
            #pragma unroll
            for (int o=16;o;o>>=1) hh2 += __shfl_xor_sync(~0u, hh2, o);
            if (lane==0) rs[wid] = hh2;
        }
        vv = vn;
        __syncthreads();
    }
}

// ---------------- launch ----------------
extern "C" void kernel_launch(void* const* d_in, const int* in_sizes, int n_in,
                              void* d_out, int out_size)
{
    (void)in_sizes; (void)n_in; (void)out_size;
    const float* keys   = (const float*)d_in[0];
    const float* values = (const float*)d_in[1];
    const float* w1     = (const float*)d_in[2];
    const float* w2     = (const float*)d_in[3];
    float* out       = (float*)d_out;
    float* out_preds = out;                 // [B,T,D]
    float* out_surp  = out + B_*T_*D_;      // [B,T]

    k_norm<<<B_*T_, D_>>>(keys);
    k_gram<<<B_*T_, 256>>>();
    dim3 gp1(H_/32, B_);
    k_p1<<<gp1, 256>>>(w1);

    const size_t f32_cnt =
        (size_t)64*132 + 64*132 + 64*264 + 16*132 + 512
        + 128 + 128 + 256 + 324 + 256 + 64*5 + 68 + 8*5;
    const size_t smem_bytes = f32_cnt * sizeof(float);
    cudaFuncSetAttribute(k_main, cudaFuncAttributeMaxDynamicSharedMemorySize,
                         (int)smem_bytes);
    k_main<<<B_*CPB, NT, smem_bytes>>>(values, w2, out_preds, out_surp);
}